// round 16
// baseline (speedup 1.0000x reference)
#include <cuda_runtime.h>
#include <cuda_fp16.h>
#include <cstdint>
#include <cstddef>

// ===========================================================================
// feature_embedding on GB300 (base compute_103: mma.sync fp16 tensor cores).
// Round 16: graph-branch overlap. Kernels identical to round 15; prep split
// into prep_struct (gcn dependency, main stream) and prep_statw (epilogue-only
// dependency, forked stream overlapping gcn).
//  B=4, N=2048, DEST=64, NET=256, INPUT=448
// ===========================================================================

namespace {
constexpr int kB     = 4;
constexpr int kN     = 2048;
constexpr int kINPUT = 448;
constexpr int BM     = 128;
constexpr int BK     = 64;           // k (nodes) per iter (4 x m16n8k16)
constexpr int SB     = 3;            // B cp.async stages
constexpr int NUM_K  = kN / BK;      // 32
constexpr int TILE_A16 = BM * BK * 2;            // 16 KB fp16 A tile
constexpr int TILE_B16 = BK * 128 * 2;           // 16 KB fp16 B tile (node-major)
constexpr int A_REGION = 2 * TILE_A16;           // A double buffer 32 KB
constexpr int SMEM_GCN = A_REGION + SB * TILE_B16;   // 80 KB

// epilogue smem layout (bytes) — 64-row tiles
constexpr int oH  = 0;            // H16 tile  64 x 272B
constexpr int oWc = 17408;        // WcT       64 x 272B
constexpr int oS  = 34816;        // stat16    64 x 528B
constexpr int oWe = 68608;        // WeT slice 64 x 528B
constexpr int SMEM_EPI = 102400;
}

// scratch
__device__ __align__(1024) __half g_B16   [(size_t)kB * kN * 128];  // struct fp16, node-major
__device__ __align__(1024) __half g_H16   [(size_t)kB * kN * 256];  // [hf|hb] fp16
__device__ __align__(1024) __half g_stat16[(size_t)kB * kN * 256];  // stat fp16
__device__ __align__(256)  __half g_WcT   [2 * 64 * 128];           // [mat][n][k]
__device__ __align__(256)  __half g_WeT   [128 * 256];              // [n][k]

// ---------------------------------------------------------------------------
// helpers
// ---------------------------------------------------------------------------
__device__ __forceinline__ uint32_t smem_u32(const void* p) {
    uint32_t a;
    asm("{ .reg .u64 t; cvta.to.shared.u64 t, %1; cvt.u32.u64 %0, t; }"
        : "=r"(a) : "l"(p));
    return a;
}
__device__ __forceinline__ void cp_async16(uint32_t dst, const void* src) {
    asm volatile("cp.async.cg.shared.global [%0], [%1], 16;"
                 :: "r"(dst), "l"(src) : "memory");
}
__device__ __forceinline__ void cp_commit() {
    asm volatile("cp.async.commit_group;" ::: "memory");
}
template <int N>
__device__ __forceinline__ void cp_wait() {
    asm volatile("cp.async.wait_group %0;" :: "n"(N) : "memory");
}
__device__ __forceinline__ void ldsm_x4(uint32_t r[4], uint32_t addr) {
    asm volatile("ldmatrix.sync.aligned.m8n8.x4.shared.b16 {%0,%1,%2,%3}, [%4];"
                 : "=r"(r[0]), "=r"(r[1]), "=r"(r[2]), "=r"(r[3]) : "r"(addr));
}
__device__ __forceinline__ void ldsm_x4_trans(uint32_t r[4], uint32_t addr) {
    asm volatile("ldmatrix.sync.aligned.m8n8.x4.trans.shared.b16 {%0,%1,%2,%3}, [%4];"
                 : "=r"(r[0]), "=r"(r[1]), "=r"(r[2]), "=r"(r[3]) : "r"(addr));
}
__device__ __forceinline__ void sts_v4(uint32_t addr, uint32_t x, uint32_t y,
                                       uint32_t z, uint32_t w) {
    asm volatile("st.shared.v4.b32 [%0], {%1,%2,%3,%4};"
                 :: "r"(addr), "r"(x), "r"(y), "r"(z), "r"(w) : "memory");
}
__device__ __forceinline__ uint32_t pack_h2(float lo, float hi) {
    __half2 h = __floats2half2_rn(lo, hi);
    return *reinterpret_cast<uint32_t*>(&h);
}
__device__ __forceinline__ void mma_f16(float c[4], const uint32_t a[4],
                                        const uint32_t b[2]) {
    asm volatile(
        "mma.sync.aligned.m16n8k16.row.col.f32.f16.f16.f32 "
        "{%0,%1,%2,%3}, {%4,%5,%6,%7}, {%8,%9}, {%0,%1,%2,%3};"
        : "+f"(c[0]), "+f"(c[1]), "+f"(c[2]), "+f"(c[3])
        : "r"(a[0]), "r"(a[1]), "r"(a[2]), "r"(a[3]), "r"(b[0]), "r"(b[1]));
}

// ---------------------------------------------------------------------------
// prep_struct: struct fp32 -> g_B16 fp16 (node-major). Pure streaming, MLP=8.
// grid 128 x 256.
// ---------------------------------------------------------------------------
__global__ void __launch_bounds__(256) prep_struct(const float* __restrict__ nfeat) {
    const int base = blockIdx.x * 2048 + threadIdx.x;
    float4 x[8];
#pragma unroll
    for (int k = 0; k < 8; ++k) {
        const int v = base + k * 256;        // 0..262143
        const int row = v >> 5, c4 = v & 31;
        x[k] = *(const float4*)(nfeat + (size_t)row * kINPUT + 64 + c4 * 4);
    }
#pragma unroll
    for (int k = 0; k < 8; ++k) {
        const int v = base + k * 256;
        const int row = v >> 5, c4 = v & 31;
        uint2 u;
        u.x = pack_h2(x[k].x, x[k].y);
        u.y = pack_h2(x[k].z, x[k].w);
        *(uint2*)(g_B16 + (size_t)row * 128 + c4 * 4) = u;
    }
}

// ---------------------------------------------------------------------------
// prep_statw: stat fp32 -> g_stat16 + weight transposes. Runs on a forked
// stream concurrently with prep_struct + gcn (only the epilogue needs it).
// grid 320 x 256: blocks [0,256) stat (MLP=8), [256,320) weights.
// ---------------------------------------------------------------------------
__global__ void __launch_bounds__(256) prep_statw(
    const float* __restrict__ nfeat,
    const float* __restrict__ Wf, const float* __restrict__ Wb,
    const float* __restrict__ We) {
    const int bx = blockIdx.x;
    const int tid = threadIdx.x;
    if (bx < 256) {
        const int base = bx * 2048 + tid;
        float4 x[8];
#pragma unroll
        for (int k = 0; k < 8; ++k) {
            const int v = base + k * 256;    // 0..524287
            const int row = v >> 6, c4 = v & 63;
            x[k] = *(const float4*)(nfeat + (size_t)row * kINPUT + 192 + c4 * 4);
        }
#pragma unroll
        for (int k = 0; k < 8; ++k) {
            const int v = base + k * 256;
            const int row = v >> 6, c4 = v & 63;
            uint2 u;
            u.x = pack_h2(x[k].x, x[k].y);
            u.y = pack_h2(x[k].z, x[k].w);
            *(uint2*)(g_stat16 + (size_t)row * 256 + c4 * 4) = u;
        }
    } else {
        const int t = (bx - 256) * 256 + tid;            // 0..16383
        for (int i = t; i < 128 * 256; i += 16384) {     // WeT
            const int n = i >> 8, k = i & 255;
            g_WeT[i] = __float2half_rn(We[k * 128 + n]);
        }
        if (t < 64 * 128) {       // WcT (both mats)
            const int n = t >> 7, k = t & 127;
            g_WcT[t]        = __float2half_rn(Wf[k * 64 + n]);
            g_WcT[8192 + t] = __float2half_rn(Wb[k * 64 + n]);
        }
    }
}

// ---------------------------------------------------------------------------
// Kernel A: H16-tile[128,128] = adj_tile[128,2048] @ struct[2048,128]
// (IDENTICAL to round 15 — trans-ldmatrix B path, at fallback-HMMA floor.)
// ---------------------------------------------------------------------------
__global__ void __launch_bounds__(256, 1) gcn_mma_kernel(
    const float* __restrict__ adjF, const float* __restrict__ adjB) {
    extern __shared__ char smem[];
    const uint32_t sbA = smem_u32(smem);
    const uint32_t sbB = sbA + A_REGION;

    const int tid  = threadIdx.x;
    const int warp = tid >> 5;
    const int lane = tid & 31;
    const int lr   = lane >> 2;
    const int lc   = lane & 3;
    const int wm   = (warp >> 2) * 64;
    const int wn   = (warp & 3) * 32;

    const int m0  = blockIdx.x * BM;
    const int b   = blockIdx.y;
    const int mat = blockIdx.z;
    const float* adj = mat ? adjB : adjF;

    const float* srcA[4];
    uint32_t dstA[4];
#pragma unroll
    for (int q = 0; q < 4; ++q) {
        const int idx = q * 256 + tid;
        const int row = idx >> 3;
        const int vec = idx & 7;
        srcA[q] = adj + ((size_t)(b * kN + m0 + row)) * kN + vec * 8;
        dstA[q] = (uint32_t)(row * 128 + ((vec ^ (row & 7)) << 4));
    }
    const __half* srcB[4];
    uint32_t dstB[4];
#pragma unroll
    for (int q = 0; q < 4; ++q) {
        const int idx = q * 256 + tid;
        const int node  = idx >> 4;
        const int chunk = idx & 15;
        srcB[q] = g_B16 + ((size_t)(b * kN + node)) * 128 + chunk * 8;
        dstB[q] = (uint32_t)(node * 256 + ((chunk ^ (node & 7)) << 4));
    }

    const int g  = lane >> 3;
    const int tr = lane & 7;
    uint32_t aLdsm[4];
#pragma unroll
    for (int mf = 0; mf < 4; ++mf) {
        const int row = wm + mf * 16 + (g & 1) * 8 + tr;
        aLdsm[mf] = (uint32_t)(row * 128 + (((g >> 1) ^ (row & 7)) << 4));
    }
    uint32_t bT[2];
#pragma unroll
    for (int p = 0; p < 2; ++p) {
        const int node = (g & 1) * 8 + tr;
        const int chunk = (wn >> 3) + 2 * p + (g >> 1);
        bT[p] = (uint32_t)(node * 256 + ((chunk ^ tr) << 4));
    }

    float c[4][4][4];
#pragma unroll
    for (int mf = 0; mf < 4; ++mf)
#pragma unroll
        for (int nb = 0; nb < 4; ++nb)
#pragma unroll
            for (int r = 0; r < 4; ++r) c[mf][nb][r] = 0.0f;

#pragma unroll
    for (int s = 0; s < SB - 1; ++s) {
#pragma unroll
        for (int q = 0; q < 4; ++q)
            cp_async16(sbB + s * TILE_B16 + dstB[q], srcB[q] + (size_t)s * BK * 128);
        cp_commit();
    }
    float4 rA[4][2];
#pragma unroll
    for (int q = 0; q < 4; ++q) {
        rA[q][0] = *(const float4*)(srcA[q]);
        rA[q][1] = *(const float4*)(srcA[q] + 4);
    }
#pragma unroll
    for (int q = 0; q < 4; ++q)
        sts_v4(sbA + dstA[q],
               pack_h2(rA[q][0].x, rA[q][0].y), pack_h2(rA[q][0].z, rA[q][0].w),
               pack_h2(rA[q][1].x, rA[q][1].y), pack_h2(rA[q][1].z, rA[q][1].w));
#pragma unroll
    for (int q = 0; q < 4; ++q) {
        rA[q][0] = *(const float4*)(srcA[q] + BK);
        rA[q][1] = *(const float4*)(srcA[q] + BK + 4);
    }

    for (int i = 0; i < NUM_K; ++i) {
        cp_wait<SB - 2>();
        __syncthreads();

        if (i + 1 < NUM_K) {
            const uint32_t aNext = sbA + (uint32_t)(((i + 1) & 1) * TILE_A16);
#pragma unroll
            for (int q = 0; q < 4; ++q)
                sts_v4(aNext + dstA[q],
                       pack_h2(rA[q][0].x, rA[q][0].y), pack_h2(rA[q][0].z, rA[q][0].w),
                       pack_h2(rA[q][1].x, rA[q][1].y), pack_h2(rA[q][1].z, rA[q][1].w));
        }
        if (i + 2 < NUM_K) {
            const int kof = (i + 2) * BK;
#pragma unroll
            for (int q = 0; q < 4; ++q) {
                rA[q][0] = *(const float4*)(srcA[q] + kof);
                rA[q][1] = *(const float4*)(srcA[q] + kof + 4);
            }
#pragma unroll
            for (int q = 0; q < 4; ++q)
                cp_async16(sbB + ((i + 2) % SB) * TILE_B16 + dstB[q],
                           srcB[q] + (size_t)(i + 2) * BK * 128);
        }
        cp_commit();

        const uint32_t aSlot = sbA + (uint32_t)((i & 1) * TILE_A16);
        const uint32_t bSlot = sbB + (uint32_t)((i % SB) * TILE_B16);
#pragma unroll
        for (int ks = 0; ks < 4; ++ks) {
            const uint32_t kx = (uint32_t)(ks << 5);
            const uint32_t kb = (uint32_t)(ks << 12);
            uint32_t a[4][4];
#pragma unroll
            for (int mf = 0; mf < 4; ++mf)
                ldsm_x4(a[mf], (aSlot + aLdsm[mf]) ^ kx);
            uint32_t bf[4][4];
#pragma unroll
            for (int p = 0; p < 2; ++p)
                ldsm_x4_trans(bf[p * 2], bSlot + bT[p] + kb);
#pragma unroll
            for (int mf = 0; mf < 4; ++mf) {
#pragma unroll
                for (int p = 0; p < 2; ++p) {
                    mma_f16(c[mf][p * 2],     a[mf], &bf[p * 2][0]);
                    mma_f16(c[mf][p * 2 + 1], a[mf], &bf[p * 2][2]);
                }
            }
        }
    }

#pragma unroll
    for (int mf = 0; mf < 4; ++mf) {
        const int row = m0 + wm + mf * 16 + lr;
        const size_t base = ((size_t)(b * kN + row)) * 256 + mat * 128;
#pragma unroll
        for (int nb = 0; nb < 4; ++nb) {
            const int col = wn + nb * 8 + lc * 2;
            *reinterpret_cast<uint32_t*>(g_H16 + base + col) =
                pack_h2(c[mf][nb][0], c[mf][nb][1]);
            *reinterpret_cast<uint32_t*>(g_H16 + base + 8 * 256 + col) =
                pack_h2(c[mf][nb][2], c[mf][nb][3]);
        }
    }
}

// ---------------------------------------------------------------------------
// Kernel B: mma epilogue (IDENTICAL to round 15 / round-13 best).
// ---------------------------------------------------------------------------
__global__ void __launch_bounds__(256, 2) epilogue_mma(
    const float* __restrict__ nfeat,
    const float* __restrict__ bfv, const float* __restrict__ bbv,
    const float* __restrict__ be,  float* __restrict__ out) {
    extern __shared__ char smem[];
    const uint32_t sb = smem_u32(smem);

    const int tid  = threadIdx.x;
    const int warp = tid >> 5;
    const int lane = tid & 31;
    const int lr   = lane >> 2;
    const int lc   = lane & 3;
    const int wm   = (warp >> 2) * 32;
    const int wn   = (warp & 3) * 16;

    const int r0  = blockIdx.x * 64;
    const int mat = blockIdx.y;

    for (int idx = tid; idx < 1024; idx += 256) {
        const int row = idx >> 4, v = idx & 15;
        cp_async16(sb + oH + row * 272 + v * 16,
                   g_H16 + ((size_t)(r0 + row)) * 256 + mat * 128 + v * 8);
    }
    for (int idx = tid; idx < 1024; idx += 256) {
        const int row = idx >> 4, v = idx & 15;
        cp_async16(sb + oWc + row * 272 + v * 16,
                   g_WcT + mat * 64 * 128 + row * 128 + v * 8);
    }
    cp_commit();
    for (int idx = tid; idx < 2048; idx += 256) {
        const int row = idx >> 5, v = idx & 31;
        cp_async16(sb + oS + row * 528 + v * 16,
                   g_stat16 + ((size_t)(r0 + row)) * 256 + v * 8);
    }
    for (int idx = tid; idx < 2048; idx += 256) {
        const int row = idx >> 5, v = idx & 31;
        cp_async16(sb + oWe + row * 528 + v * 16,
                   g_WeT + ((size_t)(mat * 64 + row)) * 256 + v * 8);
    }
    cp_commit();

    cp_wait<1>();
    __syncthreads();

    const int g   = lane >> 3;
    const int tr2 = lane & 7;

    uint32_t aE1[2];
#pragma unroll
    for (int mf = 0; mf < 2; ++mf)
        aE1[mf] = sb + oH + (uint32_t)((wm + mf * 16 + (g & 1) * 8 + tr2) * 272)
                 + (uint32_t)((g >> 1) << 4);
    const uint32_t bE1 = sb + oWc + (uint32_t)((wn + (g >> 1) * 8 + tr2) * 272)
                 + (uint32_t)((g & 1) << 4);

    float c1[2][2][4];
#pragma unroll
    for (int mf = 0; mf < 2; ++mf)
#pragma unroll
        for (int nb = 0; nb < 2; ++nb)
#pragma unroll
            for (int r = 0; r < 4; ++r) c1[mf][nb][r] = 0.0f;
#pragma unroll
    for (int ks = 0; ks < 8; ++ks) {
        const uint32_t ko = (uint32_t)(ks * 32);
        uint32_t a[2][4];
#pragma unroll
        for (int mf = 0; mf < 2; ++mf)
            ldsm_x4(a[mf], aE1[mf] + ko);
        uint32_t bf[4];
        ldsm_x4(bf, bE1 + ko);
#pragma unroll
        for (int mf = 0; mf < 2; ++mf) {
            mma_f16(c1[mf][0], a[mf], &bf[0]);
            mma_f16(c1[mf][1], a[mf], &bf[2]);
        }
    }

    cp_wait<0>();
    __syncthreads();

    uint32_t aE2[2];
#pragma unroll
    for (int mf = 0; mf < 2; ++mf)
        aE2[mf] = sb + oS + (uint32_t)((wm + mf * 16 + (g & 1) * 8 + tr2) * 528)
                 + (uint32_t)((g >> 1) << 4);
    const uint32_t bE2 = sb + oWe + (uint32_t)((wn + (g >> 1) * 8 + tr2) * 528)
                 + (uint32_t)((g & 1) << 4);

    float c2[2][2][4];
#pragma unroll
    for (int mf = 0; mf < 2; ++mf)
#pragma unroll
        for (int nb = 0; nb < 2; ++nb)
#pragma unroll
            for (int r = 0; r < 4; ++r) c2[mf][nb][r] = 0.0f;
#pragma unroll
    for (int ks = 0; ks < 16; ++ks) {
        const uint32_t ko = (uint32_t)(ks * 32);
        uint32_t a[2][4];
#pragma unroll
        for (int mf = 0; mf < 2; ++mf)
            ldsm_x4(a[mf], aE2[mf] + ko);
        uint32_t bf[4];
        ldsm_x4(bf, bE2 + ko);
#pragma unroll
        for (int mf = 0; mf < 2; ++mf) {
            mma_f16(c2[mf][0], a[mf], &bf[0]);
            mma_f16(c2[mf][1], a[mf], &bf[2]);
        }
    }

    const float* bc = mat ? bbv : bfv;
#pragma unroll
    for (int nb = 0; nb < 2; ++nb) {
        const int cl = wn + nb * 8 + lc * 2;
        const float2 biasC = *(const float2*)(bc + cl);
        const float2 biasG = *(const float2*)(be + mat * 64 + cl);
#pragma unroll
        for (int mf = 0; mf < 2; ++mf) {
#pragma unroll
            for (int h = 0; h < 2; ++h) {
                const int row = r0 + wm + mf * 16 + lr + h * 8;
                const float2 dyn = *(const float2*)(nfeat + (size_t)row * kINPUT + cl);
                const float g0 = 1.0f / (1.0f + __expf(-(c2[mf][nb][2 * h]     + biasG.x)));
                const float g1 = 1.0f / (1.0f + __expf(-(c2[mf][nb][2 * h + 1] + biasG.y)));
                float2 o;
                o.x = (c1[mf][nb][2 * h]     + biasC.x) * dyn.x * g0;
                o.y = (c1[mf][nb][2 * h + 1] + biasC.y) * dyn.y * g1;
                *(float2*)(out + (size_t)row * 128 + mat * 64 + cl) = o;
            }
        }
    }
}

// ---------------------------------------------------------------------------
extern "C" void kernel_launch(void* const* d_in, const int* in_sizes, int n_in,
                              void* d_out, int out_size) {
    (void)in_sizes; (void)n_in; (void)out_size;
    const float* nfeat = (const float*)d_in[0];
    const float* adjF  = (const float*)d_in[1];
    const float* adjB  = (const float*)d_in[2];
    const float* Wf    = (const float*)d_in[3];
    const float* bfv   = (const float*)d_in[4];
    const float* Wb    = (const float*)d_in[5];
    const float* bbv   = (const float*)d_in[6];
    const float* We    = (const float*)d_in[7];
    const float* be    = (const float*)d_in[8];
    float* out = (float*)d_out;

    static cudaStream_t s2 = nullptr;
    static cudaEvent_t evFork = nullptr, evJoin = nullptr;
    static bool init_done = false;
    if (!init_done) {
        cudaFuncSetAttribute(gcn_mma_kernel,
                             cudaFuncAttributeMaxDynamicSharedMemorySize, SMEM_GCN);
        cudaFuncSetAttribute(epilogue_mma,
                             cudaFuncAttributeMaxDynamicSharedMemorySize, SMEM_EPI);
        cudaStreamCreateWithFlags(&s2, cudaStreamNonBlocking);
        cudaEventCreateWithFlags(&evFork, cudaEventDisableTiming);
        cudaEventCreateWithFlags(&evJoin, cudaEventDisableTiming);
        init_done = true;
    }

    // fork: stat+weights prep (epilogue-only dependency) overlaps struct prep
    // and the main GEMM on a second captured stream.
    cudaEventRecord(evFork, 0);
    cudaStreamWaitEvent(s2, evFork, 0);
    prep_statw<<<320, 256, 0, s2>>>(nfeat, Wf, Wb, We);
    cudaEventRecord(evJoin, s2);

    // main stream: struct prep -> gcn
    prep_struct<<<128, 256>>>(nfeat);
    gcn_mma_kernel<<<dim3(kN / BM, kB, 2), 256, SMEM_GCN>>>(adjF, adjB);

    // join, then epilogue (needs H16 + stat16 + weights)
    cudaStreamWaitEvent(0, evJoin, 0);
    epilogue_mma<<<dim3(kB * kN / 64, 2), 256, SMEM_EPI>>>(nfeat, bfv, bbv, be, out);
}

// round 17
// speedup vs baseline: 1.0673x; 1.0673x over previous
#include <cuda_runtime.h>
#include <cuda_fp16.h>
#include <cstdint>
#include <cstddef>

// ===========================================================================
// feature_embedding on GB300 (base compute_103: mma.sync fp16 tensor cores).
// Round 17: round-15 structure (best) with a single MLP-8 prep kernel.
// Serial launches (fork/join regressed: prep CTAs steal slots from the
// floor-bound gcn kernel). gcn + epilogue byte-identical to round 15.
//  B=4, N=2048, DEST=64, NET=256, INPUT=448
// ===========================================================================

namespace {
constexpr int kB     = 4;
constexpr int kN     = 2048;
constexpr int kINPUT = 448;
constexpr int BM     = 128;
constexpr int BK     = 64;           // k (nodes) per iter (4 x m16n8k16)
constexpr int SB     = 3;            // B cp.async stages
constexpr int NUM_K  = kN / BK;      // 32
constexpr int TILE_A16 = BM * BK * 2;            // 16 KB fp16 A tile
constexpr int TILE_B16 = BK * 128 * 2;           // 16 KB fp16 B tile (node-major)
constexpr int A_REGION = 2 * TILE_A16;           // A double buffer 32 KB
constexpr int SMEM_GCN = A_REGION + SB * TILE_B16;   // 80 KB

// epilogue smem layout (bytes) — 64-row tiles
constexpr int oH  = 0;            // H16 tile  64 x 272B
constexpr int oWc = 17408;        // WcT       64 x 272B
constexpr int oS  = 34816;        // stat16    64 x 528B
constexpr int oWe = 68608;        // WeT slice 64 x 528B
constexpr int SMEM_EPI = 102400;
}

// scratch
__device__ __align__(1024) __half g_B16   [(size_t)kB * kN * 128];  // struct fp16, node-major
__device__ __align__(1024) __half g_H16   [(size_t)kB * kN * 256];  // [hf|hb] fp16
__device__ __align__(1024) __half g_stat16[(size_t)kB * kN * 256];  // stat fp16
__device__ __align__(256)  __half g_WcT   [2 * 64 * 128];           // [mat][n][k]
__device__ __align__(256)  __half g_WeT   [128 * 256];              // [n][k]

// ---------------------------------------------------------------------------
// helpers
// ---------------------------------------------------------------------------
__device__ __forceinline__ uint32_t smem_u32(const void* p) {
    uint32_t a;
    asm("{ .reg .u64 t; cvta.to.shared.u64 t, %1; cvt.u32.u64 %0, t; }"
        : "=r"(a) : "l"(p));
    return a;
}
__device__ __forceinline__ void cp_async16(uint32_t dst, const void* src) {
    asm volatile("cp.async.cg.shared.global [%0], [%1], 16;"
                 :: "r"(dst), "l"(src) : "memory");
}
__device__ __forceinline__ void cp_commit() {
    asm volatile("cp.async.commit_group;" ::: "memory");
}
template <int N>
__device__ __forceinline__ void cp_wait() {
    asm volatile("cp.async.wait_group %0;" :: "n"(N) : "memory");
}
__device__ __forceinline__ void ldsm_x4(uint32_t r[4], uint32_t addr) {
    asm volatile("ldmatrix.sync.aligned.m8n8.x4.shared.b16 {%0,%1,%2,%3}, [%4];"
                 : "=r"(r[0]), "=r"(r[1]), "=r"(r[2]), "=r"(r[3]) : "r"(addr));
}
__device__ __forceinline__ void ldsm_x4_trans(uint32_t r[4], uint32_t addr) {
    asm volatile("ldmatrix.sync.aligned.m8n8.x4.trans.shared.b16 {%0,%1,%2,%3}, [%4];"
                 : "=r"(r[0]), "=r"(r[1]), "=r"(r[2]), "=r"(r[3]) : "r"(addr));
}
__device__ __forceinline__ void sts_v4(uint32_t addr, uint32_t x, uint32_t y,
                                       uint32_t z, uint32_t w) {
    asm volatile("st.shared.v4.b32 [%0], {%1,%2,%3,%4};"
                 :: "r"(addr), "r"(x), "r"(y), "r"(z), "r"(w) : "memory");
}
__device__ __forceinline__ uint32_t pack_h2(float lo, float hi) {
    __half2 h = __floats2half2_rn(lo, hi);
    return *reinterpret_cast<uint32_t*>(&h);
}
__device__ __forceinline__ void mma_f16(float c[4], const uint32_t a[4],
                                        const uint32_t b[2]) {
    asm volatile(
        "mma.sync.aligned.m16n8k16.row.col.f32.f16.f16.f32 "
        "{%0,%1,%2,%3}, {%4,%5,%6,%7}, {%8,%9}, {%0,%1,%2,%3};"
        : "+f"(c[0]), "+f"(c[1]), "+f"(c[2]), "+f"(c[3])
        : "r"(a[0]), "r"(a[1]), "r"(a[2]), "r"(a[3]), "r"(b[0]), "r"(b[1]));
}

// ---------------------------------------------------------------------------
// Prep (single launch, MLP=8 pure streaming):
//  blocks [0,128):   struct fp32 -> g_B16 fp16 (node-major)
//  blocks [128,384): stat fp32 -> g_stat16 fp16
//  blocks [384,448): weight transposes (tiny)
// ---------------------------------------------------------------------------
__global__ void __launch_bounds__(256) prep_all(
    const float* __restrict__ nfeat,
    const float* __restrict__ Wf, const float* __restrict__ Wb,
    const float* __restrict__ We) {
    const int bx = blockIdx.x;
    const int tid = threadIdx.x;
    if (bx < 128) {
        // struct: 262144 float4 total; 8 per thread (MLP=8)
        const int base = bx * 2048 + tid;
        float4 x[8];
#pragma unroll
        for (int k = 0; k < 8; ++k) {
            const int v = base + k * 256;
            const int row = v >> 5, c4 = v & 31;
            x[k] = *(const float4*)(nfeat + (size_t)row * kINPUT + 64 + c4 * 4);
        }
#pragma unroll
        for (int k = 0; k < 8; ++k) {
            const int v = base + k * 256;
            const int row = v >> 5, c4 = v & 31;
            uint2 u;
            u.x = pack_h2(x[k].x, x[k].y);
            u.y = pack_h2(x[k].z, x[k].w);
            *(uint2*)(g_B16 + (size_t)row * 128 + c4 * 4) = u;
        }
    } else if (bx < 384) {
        // stat: 524288 float4 total; 8 per thread (MLP=8)
        const int base = (bx - 128) * 2048 + tid;
        float4 x[8];
#pragma unroll
        for (int k = 0; k < 8; ++k) {
            const int v = base + k * 256;
            const int row = v >> 6, c4 = v & 63;
            x[k] = *(const float4*)(nfeat + (size_t)row * kINPUT + 192 + c4 * 4);
        }
#pragma unroll
        for (int k = 0; k < 8; ++k) {
            const int v = base + k * 256;
            const int row = v >> 6, c4 = v & 63;
            uint2 u;
            u.x = pack_h2(x[k].x, x[k].y);
            u.y = pack_h2(x[k].z, x[k].w);
            *(uint2*)(g_stat16 + (size_t)row * 256 + c4 * 4) = u;
        }
    } else {
        const int t = (bx - 384) * 256 + tid;            // 0..16383
        for (int i = t; i < 128 * 256; i += 16384) {     // WeT
            const int n = i >> 8, k = i & 255;
            g_WeT[i] = __float2half_rn(We[k * 128 + n]);
        }
        if (t < 64 * 128) {       // WcT (both mats)
            const int n = t >> 7, k = t & 127;
            g_WcT[t]        = __float2half_rn(Wf[k * 64 + n]);
            g_WcT[8192 + t] = __float2half_rn(Wb[k * 64 + n]);
        }
    }
}

// ---------------------------------------------------------------------------
// Kernel A: H16-tile[128,128] = adj_tile[128,2048] @ struct[2048,128]
// (IDENTICAL to round 15 — trans-ldmatrix B path, at fallback-HMMA floor.)
// ---------------------------------------------------------------------------
__global__ void __launch_bounds__(256, 1) gcn_mma_kernel(
    const float* __restrict__ adjF, const float* __restrict__ adjB) {
    extern __shared__ char smem[];
    const uint32_t sbA = smem_u32(smem);
    const uint32_t sbB = sbA + A_REGION;

    const int tid  = threadIdx.x;
    const int warp = tid >> 5;
    const int lane = tid & 31;
    const int lr   = lane >> 2;
    const int lc   = lane & 3;
    const int wm   = (warp >> 2) * 64;
    const int wn   = (warp & 3) * 32;

    const int m0  = blockIdx.x * BM;
    const int b   = blockIdx.y;
    const int mat = blockIdx.z;
    const float* adj = mat ? adjB : adjF;

    const float* srcA[4];
    uint32_t dstA[4];
#pragma unroll
    for (int q = 0; q < 4; ++q) {
        const int idx = q * 256 + tid;
        const int row = idx >> 3;
        const int vec = idx & 7;
        srcA[q] = adj + ((size_t)(b * kN + m0 + row)) * kN + vec * 8;
        dstA[q] = (uint32_t)(row * 128 + ((vec ^ (row & 7)) << 4));
    }
    const __half* srcB[4];
    uint32_t dstB[4];
#pragma unroll
    for (int q = 0; q < 4; ++q) {
        const int idx = q * 256 + tid;
        const int node  = idx >> 4;
        const int chunk = idx & 15;
        srcB[q] = g_B16 + ((size_t)(b * kN + node)) * 128 + chunk * 8;
        dstB[q] = (uint32_t)(node * 256 + ((chunk ^ (node & 7)) << 4));
    }

    const int g  = lane >> 3;
    const int tr = lane & 7;
    uint32_t aLdsm[4];
#pragma unroll
    for (int mf = 0; mf < 4; ++mf) {
        const int row = wm + mf * 16 + (g & 1) * 8 + tr;
        aLdsm[mf] = (uint32_t)(row * 128 + (((g >> 1) ^ (row & 7)) << 4));
    }
    uint32_t bT[2];
#pragma unroll
    for (int p = 0; p < 2; ++p) {
        const int node = (g & 1) * 8 + tr;
        const int chunk = (wn >> 3) + 2 * p + (g >> 1);
        bT[p] = (uint32_t)(node * 256 + ((chunk ^ tr) << 4));
    }

    float c[4][4][4];
#pragma unroll
    for (int mf = 0; mf < 4; ++mf)
#pragma unroll
        for (int nb = 0; nb < 4; ++nb)
#pragma unroll
            for (int r = 0; r < 4; ++r) c[mf][nb][r] = 0.0f;

#pragma unroll
    for (int s = 0; s < SB - 1; ++s) {
#pragma unroll
        for (int q = 0; q < 4; ++q)
            cp_async16(sbB + s * TILE_B16 + dstB[q], srcB[q] + (size_t)s * BK * 128);
        cp_commit();
    }
    float4 rA[4][2];
#pragma unroll
    for (int q = 0; q < 4; ++q) {
        rA[q][0] = *(const float4*)(srcA[q]);
        rA[q][1] = *(const float4*)(srcA[q] + 4);
    }
#pragma unroll
    for (int q = 0; q < 4; ++q)
        sts_v4(sbA + dstA[q],
               pack_h2(rA[q][0].x, rA[q][0].y), pack_h2(rA[q][0].z, rA[q][0].w),
               pack_h2(rA[q][1].x, rA[q][1].y), pack_h2(rA[q][1].z, rA[q][1].w));
#pragma unroll
    for (int q = 0; q < 4; ++q) {
        rA[q][0] = *(const float4*)(srcA[q] + BK);
        rA[q][1] = *(const float4*)(srcA[q] + BK + 4);
    }

    for (int i = 0; i < NUM_K; ++i) {
        cp_wait<SB - 2>();
        __syncthreads();

        if (i + 1 < NUM_K) {
            const uint32_t aNext = sbA + (uint32_t)(((i + 1) & 1) * TILE_A16);
#pragma unroll
            for (int q = 0; q < 4; ++q)
                sts_v4(aNext + dstA[q],
                       pack_h2(rA[q][0].x, rA[q][0].y), pack_h2(rA[q][0].z, rA[q][0].w),
                       pack_h2(rA[q][1].x, rA[q][1].y), pack_h2(rA[q][1].z, rA[q][1].w));
        }
        if (i + 2 < NUM_K) {
            const int kof = (i + 2) * BK;
#pragma unroll
            for (int q = 0; q < 4; ++q) {
                rA[q][0] = *(const float4*)(srcA[q] + kof);
                rA[q][1] = *(const float4*)(srcA[q] + kof + 4);
            }
#pragma unroll
            for (int q = 0; q < 4; ++q)
                cp_async16(sbB + ((i + 2) % SB) * TILE_B16 + dstB[q],
                           srcB[q] + (size_t)(i + 2) * BK * 128);
        }
        cp_commit();

        const uint32_t aSlot = sbA + (uint32_t)((i & 1) * TILE_A16);
        const uint32_t bSlot = sbB + (uint32_t)((i % SB) * TILE_B16);
#pragma unroll
        for (int ks = 0; ks < 4; ++ks) {
            const uint32_t kx = (uint32_t)(ks << 5);
            const uint32_t kb = (uint32_t)(ks << 12);
            uint32_t a[4][4];
#pragma unroll
            for (int mf = 0; mf < 4; ++mf)
                ldsm_x4(a[mf], (aSlot + aLdsm[mf]) ^ kx);
            uint32_t bf[4][4];
#pragma unroll
            for (int p = 0; p < 2; ++p)
                ldsm_x4_trans(bf[p * 2], bSlot + bT[p] + kb);
#pragma unroll
            for (int mf = 0; mf < 4; ++mf) {
#pragma unroll
                for (int p = 0; p < 2; ++p) {
                    mma_f16(c[mf][p * 2],     a[mf], &bf[p * 2][0]);
                    mma_f16(c[mf][p * 2 + 1], a[mf], &bf[p * 2][2]);
                }
            }
        }
    }

#pragma unroll
    for (int mf = 0; mf < 4; ++mf) {
        const int row = m0 + wm + mf * 16 + lr;
        const size_t base = ((size_t)(b * kN + row)) * 256 + mat * 128;
#pragma unroll
        for (int nb = 0; nb < 4; ++nb) {
            const int col = wn + nb * 8 + lc * 2;
            *reinterpret_cast<uint32_t*>(g_H16 + base + col) =
                pack_h2(c[mf][nb][0], c[mf][nb][1]);
            *reinterpret_cast<uint32_t*>(g_H16 + base + 8 * 256 + col) =
                pack_h2(c[mf][nb][2], c[mf][nb][3]);
        }
    }
}

// ---------------------------------------------------------------------------
// Kernel B: mma epilogue (IDENTICAL to round 15 / round-13 best).
// ---------------------------------------------------------------------------
__global__ void __launch_bounds__(256, 2) epilogue_mma(
    const float* __restrict__ nfeat,
    const float* __restrict__ bfv, const float* __restrict__ bbv,
    const float* __restrict__ be,  float* __restrict__ out) {
    extern __shared__ char smem[];
    const uint32_t sb = smem_u32(smem);

    const int tid  = threadIdx.x;
    const int warp = tid >> 5;
    const int lane = tid & 31;
    const int lr   = lane >> 2;
    const int lc   = lane & 3;
    const int wm   = (warp >> 2) * 32;
    const int wn   = (warp & 3) * 16;

    const int r0  = blockIdx.x * 64;
    const int mat = blockIdx.y;

    for (int idx = tid; idx < 1024; idx += 256) {
        const int row = idx >> 4, v = idx & 15;
        cp_async16(sb + oH + row * 272 + v * 16,
                   g_H16 + ((size_t)(r0 + row)) * 256 + mat * 128 + v * 8);
    }
    for (int idx = tid; idx < 1024; idx += 256) {
        const int row = idx >> 4, v = idx & 15;
        cp_async16(sb + oWc + row * 272 + v * 16,
                   g_WcT + mat * 64 * 128 + row * 128 + v * 8);
    }
    cp_commit();
    for (int idx = tid; idx < 2048; idx += 256) {
        const int row = idx >> 5, v = idx & 31;
        cp_async16(sb + oS + row * 528 + v * 16,
                   g_stat16 + ((size_t)(r0 + row)) * 256 + v * 8);
    }
    for (int idx = tid; idx < 2048; idx += 256) {
        const int row = idx >> 5, v = idx & 31;
        cp_async16(sb + oWe + row * 528 + v * 16,
                   g_WeT + ((size_t)(mat * 64 + row)) * 256 + v * 8);
    }
    cp_commit();

    cp_wait<1>();
    __syncthreads();

    const int g   = lane >> 3;
    const int tr2 = lane & 7;

    uint32_t aE1[2];
#pragma unroll
    for (int mf = 0; mf < 2; ++mf)
        aE1[mf] = sb + oH + (uint32_t)((wm + mf * 16 + (g & 1) * 8 + tr2) * 272)
                 + (uint32_t)((g >> 1) << 4);
    const uint32_t bE1 = sb + oWc + (uint32_t)((wn + (g >> 1) * 8 + tr2) * 272)
                 + (uint32_t)((g & 1) << 4);

    float c1[2][2][4];
#pragma unroll
    for (int mf = 0; mf < 2; ++mf)
#pragma unroll
        for (int nb = 0; nb < 2; ++nb)
#pragma unroll
            for (int r = 0; r < 4; ++r) c1[mf][nb][r] = 0.0f;
#pragma unroll
    for (int ks = 0; ks < 8; ++ks) {
        const uint32_t ko = (uint32_t)(ks * 32);
        uint32_t a[2][4];
#pragma unroll
        for (int mf = 0; mf < 2; ++mf)
            ldsm_x4(a[mf], aE1[mf] + ko);
        uint32_t bf[4];
        ldsm_x4(bf, bE1 + ko);
#pragma unroll
        for (int mf = 0; mf < 2; ++mf) {
            mma_f16(c1[mf][0], a[mf], &bf[0]);
            mma_f16(c1[mf][1], a[mf], &bf[2]);
        }
    }

    cp_wait<0>();
    __syncthreads();

    uint32_t aE2[2];
#pragma unroll
    for (int mf = 0; mf < 2; ++mf)
        aE2[mf] = sb + oS + (uint32_t)((wm + mf * 16 + (g & 1) * 8 + tr2) * 528)
                 + (uint32_t)((g >> 1) << 4);
    const uint32_t bE2 = sb + oWe + (uint32_t)((wn + (g >> 1) * 8 + tr2) * 528)
                 + (uint32_t)((g & 1) << 4);

    float c2[2][2][4];
#pragma unroll
    for (int mf = 0; mf < 2; ++mf)
#pragma unroll
        for (int nb = 0; nb < 2; ++nb)
#pragma unroll
            for (int r = 0; r < 4; ++r) c2[mf][nb][r] = 0.0f;
#pragma unroll
    for (int ks = 0; ks < 16; ++ks) {
        const uint32_t ko = (uint32_t)(ks * 32);
        uint32_t a[2][4];
#pragma unroll
        for (int mf = 0; mf < 2; ++mf)
            ldsm_x4(a[mf], aE2[mf] + ko);
        uint32_t bf[4];
        ldsm_x4(bf, bE2 + ko);
#pragma unroll
        for (int mf = 0; mf < 2; ++mf) {
            mma_f16(c2[mf][0], a[mf], &bf[0]);
            mma_f16(c2[mf][1], a[mf], &bf[2]);
        }
    }

    const float* bc = mat ? bbv : bfv;
#pragma unroll
    for (int nb = 0; nb < 2; ++nb) {
        const int cl = wn + nb * 8 + lc * 2;
        const float2 biasC = *(const float2*)(bc + cl);
        const float2 biasG = *(const float2*)(be + mat * 64 + cl);
#pragma unroll
        for (int mf = 0; mf < 2; ++mf) {
#pragma unroll
            for (int h = 0; h < 2; ++h) {
                const int row = r0 + wm + mf * 16 + lr + h * 8;
                const float2 dyn = *(const float2*)(nfeat + (size_t)row * kINPUT + cl);
                const float g0 = 1.0f / (1.0f + __expf(-(c2[mf][nb][2 * h]     + biasG.x)));
                const float g1 = 1.0f / (1.0f + __expf(-(c2[mf][nb][2 * h + 1] + biasG.y)));
                float2 o;
                o.x = (c1[mf][nb][2 * h]     + biasC.x) * dyn.x * g0;
                o.y = (c1[mf][nb][2 * h + 1] + biasC.y) * dyn.y * g1;
                *(float2*)(out + (size_t)row * 128 + mat * 64 + cl) = o;
            }
        }
    }
}

// ---------------------------------------------------------------------------
extern "C" void kernel_launch(void* const* d_in, const int* in_sizes, int n_in,
                              void* d_out, int out_size) {
    (void)in_sizes; (void)n_in; (void)out_size;
    const float* nfeat = (const float*)d_in[0];
    const float* adjF  = (const float*)d_in[1];
    const float* adjB  = (const float*)d_in[2];
    const float* Wf    = (const float*)d_in[3];
    const float* bfv   = (const float*)d_in[4];
    const float* Wb    = (const float*)d_in[5];
    const float* bbv   = (const float*)d_in[6];
    const float* We    = (const float*)d_in[7];
    const float* be    = (const float*)d_in[8];
    float* out = (float*)d_out;

    static bool attr_set = false;
    if (!attr_set) {
        cudaFuncSetAttribute(gcn_mma_kernel,
                             cudaFuncAttributeMaxDynamicSharedMemorySize, SMEM_GCN);
        cudaFuncSetAttribute(epilogue_mma,
                             cudaFuncAttributeMaxDynamicSharedMemorySize, SMEM_EPI);
        attr_set = true;
    }

    prep_all<<<448, 256>>>(nfeat, Wf, Wb, We);
    gcn_mma_kernel<<<dim3(kN / BM, kB, 2), 256, SMEM_GCN>>>(adjF, adjB);
    epilogue_mma<<<dim3(kB * kN / 64, 2), 256, SMEM_EPI>>>(nfeat, bfv, bbv, be, out);
}